// round 3
// baseline (speedup 1.0000x reference)
#include <cuda_runtime.h>
#include <cuda_bf16.h>

// Problem constants
#define NS   524288      // samples
#define HD   64          // hidden width
#define NVAR 16          // variables
#define TPB  128         // threads per block (4 warps)
#define MT   64          // samples per tile (16 rows per warp)
#define CTAS 512         // blocks per variable-kernel
#define ITERS (NS / (MT * CTAS))   // 16 tiles per CTA
#define APAD 66          // bf16 row stride (132B -> conflict-free-ish banks)

// bf16x2 pack
__device__ __forceinline__ unsigned pack_bf2(float a, float b) {
    __nv_bfloat162 t = __floats2bfloat162_rn(a, b);
    return *reinterpret_cast<unsigned*>(&t);
}

#define MMA_BF16(cc, aa, bb0, bb1)                                          \
    asm volatile(                                                           \
        "mma.sync.aligned.m16n8k16.row.col.f32.bf16.bf16.f32 "              \
        "{%0,%1,%2,%3}, {%4,%5,%6,%7}, {%8,%9}, {%0,%1,%2,%3};"             \
        : "+f"(cc[0]), "+f"(cc[1]), "+f"(cc[2]), "+f"(cc[3])                \
        : "r"(aa[0]), "r"(aa[1]), "r"(aa[2]), "r"(aa[3]),                   \
          "r"(bb0), "r"(bb1))

// One causal variable: out = MLP(concat(parent, eps)) elementwise over samples.
// Layer2 (64x64) runs on tensor cores with bf16 hi/lo error-compensated split
// (3 accumulation passes -> near-fp32 precision). Layers 1/3 in fp32 FFMA.
__global__ __launch_bounds__(TPB)
void ncm_var_kernel(const float* __restrict__ noise_v,
                    const float* __restrict__ stds, int v, int inDim,
                    const float* __restrict__ w1p, const float* __restrict__ b1p,
                    const float* __restrict__ w2p, const float* __restrict__ b2p,
                    const float* __restrict__ w3p, const float* __restrict__ b3p,
                    const float* __restrict__ parent,
                    float* __restrict__ outv)
{
    __shared__ unsigned short sAhi[MT * APAD];   // h1 hi (bf16), row = sample
    __shared__ unsigned short sAlo[MT * APAD];   // h1 lo (bf16)
    __shared__ unsigned short sBhi[HD * APAD];   // W2^T hi (row = n, col = k)
    __shared__ unsigned short sBlo[HD * APAD];   // W2^T lo
    __shared__ float su[HD], sv[HD], sb1[HD], sb2[HD], sw3[HD];
    __shared__ float sb3;

    const int t = threadIdx.x;

    // ---- one-time weight prep (per CTA) ----
    for (int j = t; j < HD; j += TPB) {
        if (inDim == 2) { su[j] = w1p[j]; sv[j] = w1p[HD + j]; }
        else            { su[j] = 0.0f;   sv[j] = w1p[j]; }
        sb1[j] = b1p[j];
        sb2[j] = b2p[j];
        sw3[j] = w3p[j];
    }
    if (t == 0) sb3 = b3p[0];
    for (int idx = t; idx < HD * HD; idx += TPB) {
        int k = idx >> 6, n = idx & 63;          // W2[k][n]
        float f = w2p[idx];
        __nv_bfloat16 hi = __float2bfloat16_rn(f);
        float lof = f - __bfloat162float(hi);
        __nv_bfloat16 lo = __float2bfloat16_rn(lof);
        sBhi[n * APAD + k] = *reinterpret_cast<unsigned short*>(&hi);
        sBlo[n * APAD + k] = *reinterpret_cast<unsigned short*>(&lo);
    }
    const float stdv = fabsf(stds[v]);
    __syncthreads();

    const int lane = t & 31, warp = t >> 5;
    const int cq = lane & 3, cr = lane >> 2;     // quad-pair decomposition
    const int r0 = warp * 16;                    // warp's row base in the tile
    const int cbase = blockIdx.x * (MT * ITERS);

    for (int it = 0; it < ITERS; ++it) {
        const int sbase = cbase + it * MT;

        // ---- phase 1: layer1 (fp32) + bf16 hi/lo split into smem ----
        {
            const int sl = t & 63, half = t >> 6;
            const float e = noise_v[sbase + sl] * stdv;
            const float p = parent ? parent[sbase + sl] : 0.0f;
            #pragma unroll
            for (int j2 = 0; j2 < 32; j2 += 2) {
                const int j = half * 32 + j2;
                float h0 = fmaf(p, su[j],     fmaf(e, sv[j],     sb1[j]));
                float h1 = fmaf(p, su[j + 1], fmaf(e, sv[j + 1], sb1[j + 1]));
                h0 = fmaxf(h0, 0.0f);
                h1 = fmaxf(h1, 0.0f);
                __nv_bfloat16 h0h = __float2bfloat16_rn(h0);
                __nv_bfloat16 h1h = __float2bfloat16_rn(h1);
                float l0 = h0 - __bfloat162float(h0h);
                float l1 = h1 - __bfloat162float(h1h);
                unsigned hihi =
                    ((unsigned)*reinterpret_cast<unsigned short*>(&h1h) << 16) |
                     (unsigned)*reinterpret_cast<unsigned short*>(&h0h);
                *reinterpret_cast<unsigned*>(&sAhi[sl * APAD + j]) = hihi;
                *reinterpret_cast<unsigned*>(&sAlo[sl * APAD + j]) = pack_bf2(l0, l1);
            }
        }
        __syncthreads();

        // ---- phase 2: [16x64] @ [64x64] per warp, 3-pass compensated bf16 ----
        float c[8][4];
        #pragma unroll
        for (int nt = 0; nt < 8; ++nt) {
            c[nt][0] = 0.f; c[nt][1] = 0.f; c[nt][2] = 0.f; c[nt][3] = 0.f;
        }

        unsigned ah[4][4], al[4][4];
        #pragma unroll
        for (int kk = 0; kk < 4; ++kk) {
            const int col = kk * 16 + 2 * cq;
            ah[kk][0] = *reinterpret_cast<unsigned*>(&sAhi[(r0 + cr    ) * APAD + col]);
            ah[kk][1] = *reinterpret_cast<unsigned*>(&sAhi[(r0 + cr + 8) * APAD + col]);
            ah[kk][2] = *reinterpret_cast<unsigned*>(&sAhi[(r0 + cr    ) * APAD + col + 8]);
            ah[kk][3] = *reinterpret_cast<unsigned*>(&sAhi[(r0 + cr + 8) * APAD + col + 8]);
            al[kk][0] = *reinterpret_cast<unsigned*>(&sAlo[(r0 + cr    ) * APAD + col]);
            al[kk][1] = *reinterpret_cast<unsigned*>(&sAlo[(r0 + cr + 8) * APAD + col]);
            al[kk][2] = *reinterpret_cast<unsigned*>(&sAlo[(r0 + cr    ) * APAD + col + 8]);
            al[kk][3] = *reinterpret_cast<unsigned*>(&sAlo[(r0 + cr + 8) * APAD + col + 8]);
        }

        #pragma unroll
        for (int nt = 0; nt < 8; ++nt) {
            const int brow = nt * 8 + cr;
            #pragma unroll
            for (int kk = 0; kk < 4; ++kk) {
                const int bcol = kk * 16 + 2 * cq;
                unsigned bh0 = *reinterpret_cast<unsigned*>(&sBhi[brow * APAD + bcol]);
                unsigned bh1 = *reinterpret_cast<unsigned*>(&sBhi[brow * APAD + bcol + 8]);
                unsigned bl0 = *reinterpret_cast<unsigned*>(&sBlo[brow * APAD + bcol]);
                unsigned bl1 = *reinterpret_cast<unsigned*>(&sBlo[brow * APAD + bcol + 8]);
                MMA_BF16(c[nt], ah[kk], bh0, bh1);   // hi * hi
                MMA_BF16(c[nt], ah[kk], bl0, bl1);   // hi * lo
                MMA_BF16(c[nt], al[kk], bh0, bh1);   // lo * hi
            }
        }

        // ---- phase 3: fused bias + ReLU + layer3 dot (fp32) ----
        float acc0 = 0.0f, acc8 = 0.0f;
        #pragma unroll
        for (int nt = 0; nt < 8; ++nt) {
            const int j0 = nt * 8 + 2 * cq;
            const float bb0 = sb2[j0], bb1 = sb2[j0 + 1];
            const float ww0 = sw3[j0], ww1 = sw3[j0 + 1];
            acc0 = fmaf(fmaxf(c[nt][0] + bb0, 0.f), ww0, acc0);
            acc0 = fmaf(fmaxf(c[nt][1] + bb1, 0.f), ww1, acc0);
            acc8 = fmaf(fmaxf(c[nt][2] + bb0, 0.f), ww0, acc8);
            acc8 = fmaf(fmaxf(c[nt][3] + bb1, 0.f), ww1, acc8);
        }
        acc0 += __shfl_xor_sync(0xffffffffu, acc0, 1);
        acc0 += __shfl_xor_sync(0xffffffffu, acc0, 2);
        acc8 += __shfl_xor_sync(0xffffffffu, acc8, 1);
        acc8 += __shfl_xor_sync(0xffffffffu, acc8, 2);
        if (cq == 0) {
            outv[sbase + r0 + cr]     = acc0 + sb3;
            outv[sbase + r0 + cr + 8] = acc8 + sb3;
        }
        __syncthreads();   // protect smem before next tile's phase-1 overwrite
    }
}

extern "C" void kernel_launch(void* const* d_in, const int* in_sizes, int n_in,
                              void* d_out, int out_size)
{
    const float* noise = (const float*)d_in[0];
    const float* stds  = (const float*)d_in[1];
    const float* w0_1  = (const float*)d_in[2];
    const float* b0_1  = (const float*)d_in[3];
    const float* w0_2  = (const float*)d_in[4];
    const float* b0_2  = (const float*)d_in[5];
    const float* w0_3  = (const float*)d_in[6];
    const float* b0_3  = (const float*)d_in[7];
    const float* W1    = (const float*)d_in[8];
    const float* B1    = (const float*)d_in[9];
    const float* W2    = (const float*)d_in[10];
    const float* B2    = (const float*)d_in[11];
    const float* W3    = (const float*)d_in[12];
    const float* B3    = (const float*)d_in[13];
    float* out = (float*)d_out;

    // var 0: root (input dim 1 = noise only)
    ncm_var_kernel<<<CTAS, TPB>>>(noise, stds, 0, 1,
                                  w0_1, b0_1, w0_2, b0_2, w0_3, b0_3,
                                  nullptr, out);
    // vars 1..15: chain, each reads previous variable's samples from d_out
    for (int v = 1; v < NVAR; ++v) {
        const int m = v - 1;
        ncm_var_kernel<<<CTAS, TPB>>>(noise + (size_t)v * NS, stds, v, 2,
                                      W1 + (size_t)m * 2 * HD,
                                      B1 + (size_t)m * HD,
                                      W2 + (size_t)m * HD * HD,
                                      B2 + (size_t)m * HD,
                                      W3 + (size_t)m * HD,
                                      B3 + m,
                                      out + (size_t)(v - 1) * NS,
                                      out + (size_t)v * NS);
    }
}

// round 14
// speedup vs baseline: 2.7096x; 2.7096x over previous
#include <cuda_runtime.h>
#include <cuda_bf16.h>

// Problem constants
#define NS   524288      // samples
#define HD   64          // hidden width
#define NVAR 16          // variables
#define TPB  128         // 4 warps
#define MT   128         // samples per CTA-tile (32 rows per warp)
#define CTAS 1024
#define ITERS (NS / (MT * CTAS))   // 4 tiles per CTA

__device__ __forceinline__ unsigned bits2(__nv_bfloat162 v) {
    return *reinterpret_cast<unsigned*>(&v);
}

// fp32 pair -> (bf16x2 hi, bf16x2 lo residual)
__device__ __forceinline__ void split2(float a, float b, unsigned& hi, unsigned& lo) {
    __nv_bfloat162 h = __floats2bfloat162_rn(a, b);
    float2 hf = __bfloat1622float2(h);
    __nv_bfloat162 l = __floats2bfloat162_rn(a - hf.x, b - hf.y);
    hi = bits2(h);
    lo = bits2(l);
}

#define MMA_BF16(cc, a0, a1, a2, a3, bb0, bb1)                              \
    asm volatile(                                                           \
        "mma.sync.aligned.m16n8k16.row.col.f32.bf16.bf16.f32 "              \
        "{%0,%1,%2,%3}, {%4,%5,%6,%7}, {%8,%9}, {%0,%1,%2,%3};"             \
        : "+f"(cc[0]), "+f"(cc[1]), "+f"(cc[2]), "+f"(cc[3])                \
        : "r"(a0), "r"(a1), "r"(a2), "r"(a3), "r"(bb0), "r"(bb1))

// One causal variable. Layer1 computed per-lane directly into MMA A-fragment
// registers (no smem staging, no barriers in main loop). Layer2 on tensor
// cores, bf16 hi/lo 3-pass compensated. B prepacked in fragment order.
__global__ __launch_bounds__(TPB, 3)
void ncm_var_kernel(const float* __restrict__ noise_v,
                    const float* __restrict__ stds, int v, int inDim,
                    const float* __restrict__ w1p, const float* __restrict__ b1p,
                    const float* __restrict__ w2p, const float* __restrict__ b2p,
                    const float* __restrict__ w3p, const float* __restrict__ b3p,
                    const float* __restrict__ parent,
                    float* __restrict__ outv)
{
    // B prepacked: idx = (((nt*4 + kk)*32) + lane)*2 + pair   (pair: k, k+8)
    __shared__ unsigned sBhi[2048];   // 8 KB
    __shared__ unsigned sBlo[2048];   // 8 KB
    __shared__ float su[HD], sv[HD], sb1[HD], sb2[HD], sw3[HD];
    __shared__ float sb3v;

    const int t = threadIdx.x;

    // ---- one-time weight prep ----
    for (int j = t; j < HD; j += TPB) {
        if (inDim == 2) { su[j] = w1p[j]; sv[j] = w1p[HD + j]; }
        else            { su[j] = 0.0f;   sv[j] = w1p[j]; }
        sb1[j] = b1p[j];
        sb2[j] = b2p[j];
        sw3[j] = w3p[j];
    }
    if (t == 0) sb3v = b3p[0];
    for (int idx = t; idx < 2048; idx += TPB) {
        const int pair = idx & 1;
        const int ln   = (idx >> 1) & 31;
        const int kk   = (idx >> 6) & 3;
        const int nt   = (idx >> 8) & 7;
        const int n    = nt * 8 + (ln >> 2);
        const int k0   = kk * 16 + 2 * (ln & 3) + pair * 8;
        const float f0 = w2p[k0 * HD + n];         // W2[k][n]
        const float f1 = w2p[(k0 + 1) * HD + n];
        unsigned hi, lo;
        split2(f0, f1, hi, lo);
        sBhi[idx] = hi;
        sBlo[idx] = lo;
    }
    const float stdv = fabsf(stds[v]);
    __syncthreads();

    const int lane = t & 31, warp = t >> 5;
    const int cq = lane & 3, cr = lane >> 2;
    const int cbase = blockIdx.x * (MT * ITERS);

    for (int it = 0; it < ITERS; ++it) {
        const int tb = cbase + it * MT + warp * 32;   // warp's 32-row base

        // ---- phase 1: layer1 directly into A fragments (no smem, no sync) ----
        unsigned ah[2][4][4], al[2][4][4];
        #pragma unroll
        for (int rb = 0; rb < 2; ++rb) {
            const int row0 = tb + rb * 16 + cr;       // and row0+8
            const float e0 = noise_v[row0]     * stdv;
            const float e1 = noise_v[row0 + 8] * stdv;
            const float p0 = parent ? parent[row0]     : 0.0f;
            const float p1 = parent ? parent[row0 + 8] : 0.0f;
            #pragma unroll
            for (int kk = 0; kk < 4; ++kk) {
                const int k0 = kk * 16 + 2 * cq;
                #pragma unroll
                for (int half = 0; half < 2; ++half) {   // cols k0(+8), k0+1(+8)
                    const int c0 = k0 + half * 8;
                    const float wu0 = su[c0],  wu1 = su[c0 + 1];
                    const float wv0 = sv[c0],  wv1 = sv[c0 + 1];
                    const float bb0 = sb1[c0], bb1 = sb1[c0 + 1];
                    const float h00 = fmaxf(fmaf(p0, wu0, fmaf(e0, wv0, bb0)), 0.f);
                    const float h01 = fmaxf(fmaf(p0, wu1, fmaf(e0, wv1, bb1)), 0.f);
                    const float h10 = fmaxf(fmaf(p1, wu0, fmaf(e1, wv0, bb0)), 0.f);
                    const float h11 = fmaxf(fmaf(p1, wu1, fmaf(e1, wv1, bb1)), 0.f);
                    split2(h00, h01, ah[rb][kk][half * 2],     al[rb][kk][half * 2]);
                    split2(h10, h11, ah[rb][kk][half * 2 + 1], al[rb][kk][half * 2 + 1]);
                }
            }
        }

        // ---- phase 2: 3-pass compensated MMA, B fragments via LDS.64 ----
        float c[2][8][4];
        #pragma unroll
        for (int rb = 0; rb < 2; ++rb)
            #pragma unroll
            for (int nt = 0; nt < 8; ++nt) {
                c[rb][nt][0] = 0.f; c[rb][nt][1] = 0.f;
                c[rb][nt][2] = 0.f; c[rb][nt][3] = 0.f;
            }

        #pragma unroll
        for (int nt = 0; nt < 8; ++nt) {
            #pragma unroll
            for (int kk = 0; kk < 4; ++kk) {
                const int bidx = (((nt * 4 + kk) * 32) + lane) * 2;
                const uint2 bh = *reinterpret_cast<const uint2*>(&sBhi[bidx]);
                const uint2 bl = *reinterpret_cast<const uint2*>(&sBlo[bidx]);
                #pragma unroll
                for (int rb = 0; rb < 2; ++rb) {
                    MMA_BF16(c[rb][nt], ah[rb][kk][0], ah[rb][kk][1],
                                        ah[rb][kk][2], ah[rb][kk][3], bh.x, bh.y);
                    MMA_BF16(c[rb][nt], ah[rb][kk][0], ah[rb][kk][1],
                                        ah[rb][kk][2], ah[rb][kk][3], bl.x, bl.y);
                    MMA_BF16(c[rb][nt], al[rb][kk][0], al[rb][kk][1],
                                        al[rb][kk][2], al[rb][kk][3], bh.x, bh.y);
                }
            }
        }

        // ---- phase 3: bias + ReLU + layer3 dot, shfl-reduce over cq ----
        float acc[2][2] = {{0.f, 0.f}, {0.f, 0.f}};   // [rb][row-half]
        #pragma unroll
        for (int nt = 0; nt < 8; ++nt) {
            const int j0 = nt * 8 + 2 * cq;
            const float bb0 = sb2[j0], bb1 = sb2[j0 + 1];
            const float ww0 = sw3[j0], ww1 = sw3[j0 + 1];
            #pragma unroll
            for (int rb = 0; rb < 2; ++rb) {
                acc[rb][0] = fmaf(fmaxf(c[rb][nt][0] + bb0, 0.f), ww0, acc[rb][0]);
                acc[rb][0] = fmaf(fmaxf(c[rb][nt][1] + bb1, 0.f), ww1, acc[rb][0]);
                acc[rb][1] = fmaf(fmaxf(c[rb][nt][2] + bb0, 0.f), ww0, acc[rb][1]);
                acc[rb][1] = fmaf(fmaxf(c[rb][nt][3] + bb1, 0.f), ww1, acc[rb][1]);
            }
        }
        #pragma unroll
        for (int rb = 0; rb < 2; ++rb) {
            acc[rb][0] += __shfl_xor_sync(0xffffffffu, acc[rb][0], 1);
            acc[rb][0] += __shfl_xor_sync(0xffffffffu, acc[rb][0], 2);
            acc[rb][1] += __shfl_xor_sync(0xffffffffu, acc[rb][1], 1);
            acc[rb][1] += __shfl_xor_sync(0xffffffffu, acc[rb][1], 2);
            if (cq == 0) {
                const int row0 = tb + rb * 16 + cr;
                outv[row0]     = acc[rb][0] + sb3v;
                outv[row0 + 8] = acc[rb][1] + sb3v;
            }
        }
    }
}

extern "C" void kernel_launch(void* const* d_in, const int* in_sizes, int n_in,
                              void* d_out, int out_size)
{
    const float* noise = (const float*)d_in[0];
    const float* stds  = (const float*)d_in[1];
    const float* w0_1  = (const float*)d_in[2];
    const float* b0_1  = (const float*)d_in[3];
    const float* w0_2  = (const float*)d_in[4];
    const float* b0_2  = (const float*)d_in[5];
    const float* w0_3  = (const float*)d_in[6];
    const float* b0_3  = (const float*)d_in[7];
    const float* W1    = (const float*)d_in[8];
    const float* B1    = (const float*)d_in[9];
    const float* W2    = (const float*)d_in[10];
    const float* B2    = (const float*)d_in[11];
    const float* W3    = (const float*)d_in[12];
    const float* B3    = (const float*)d_in[13];
    float* out = (float*)d_out;

    // var 0: root (input dim 1 = noise only)
    ncm_var_kernel<<<CTAS, TPB>>>(noise, stds, 0, 1,
                                  w0_1, b0_1, w0_2, b0_2, w0_3, b0_3,
                                  nullptr, out);
    // vars 1..15: chain, each reads previous variable's samples from d_out
    for (int v = 1; v < NVAR; ++v) {
        const int m = v - 1;
        ncm_var_kernel<<<CTAS, TPB>>>(noise + (size_t)v * NS, stds, v, 2,
                                      W1 + (size_t)m * 2 * HD,
                                      B1 + (size_t)m * HD,
                                      W2 + (size_t)m * HD * HD,
                                      B2 + (size_t)m * HD,
                                      W3 + (size_t)m * HD,
                                      B3 + m,
                                      out + (size_t)(v - 1) * NS,
                                      out + (size_t)v * NS);
    }
}